// round 16
// baseline (speedup 1.0000x reference)
#include <cuda_runtime.h>
#include <stdint.h>

#define DIM        3200
#define HID        6400
#define NTOK       16384   // 8 * 2048
#define NEW_START  32000

#define MAXM       64      // fast path covers rows [0, 64)
#define BN         128     // n per block
#define BK         32      // k per stage
#define KCHUNK     160     // k per split (5 stages)
#define SPLITS1    20      // layer1: K=3200
#define SPLITS2    40      // layer2: K=6400

#define CP_BLKS    148     // persistent copy: exactly 1 block per SM

// smem: 3-stage ring; per stage A[64][36] f32 (9216B) + B[32][136] f32 (17408B)
#define AS_LD      36
#define BS_LD      136     // 128 + 8 pad; conflict-free frag reads
#define A_BYTES    9216
#define B_ROW_B    (BS_LD * 4)                // 544
#define STAGE_B    (A_BYTES + BK * B_ROW_B)   // 26624
#define SMEM_B     (3 * STAGE_B)              // 79872

// fallback tiling (rows >= 64; early-exits normally)
#define FBM 64
#define FBN 64
#define FBK 16
#define FTM 4
#define FTN 4

// ---------------- scratch (static device globals; no allocation) ----------------
__device__ int   g_count;
__device__ int   g_tok[NTOK];
__device__ float g_H[(size_t)NTOK * HID];            // hidden activations
__device__ float g_P[(size_t)8192000];               // split-K partials

// ---------------- helpers ----------------
__device__ __forceinline__ uint32_t smem_u32(const void* p) {
    uint32_t a;
    asm("{ .reg .u64 t; cvta.to.shared.u64 t, %1; cvt.u32.u64 %0, t; }" : "=r"(a) : "l"(p));
    return a;
}
__device__ __forceinline__ void cp16(uint32_t dst, const void* src, int srcsz) {
    asm volatile("cp.async.ca.shared.global [%0], [%1], 16, %2;"
                 :: "r"(dst), "l"(__cvta_generic_to_global(src)), "r"(srcsz) : "memory");
}
#define CP_COMMIT() asm volatile("cp.async.commit_group;" ::: "memory")
#define CP_WAIT2()  asm volatile("cp.async.wait_group 2;" ::: "memory")

__device__ __forceinline__ void mma_tf32(float* c, const uint32_t* a, const uint32_t* b) {
    asm volatile(
        "mma.sync.aligned.m16n8k8.row.col.f32.tf32.tf32.f32 "
        "{%0,%1,%2,%3}, {%4,%5,%6,%7}, {%8,%9}, {%0,%1,%2,%3};"
        : "+f"(c[0]), "+f"(c[1]), "+f"(c[2]), "+f"(c[3])
        : "r"(a[0]), "r"(a[1]), "r"(a[2]), "r"(a[3]), "r"(b[0]), "r"(b[1]));
}

// ---------------- kernel 0/1: reset + compact ----------------
__global__ void k_reset() { g_count = 0; }

__global__ void k_compact(const int* __restrict__ ids) {
    int t = blockIdx.x * blockDim.x + threadIdx.x;
    if (t < NTOK && ids[t] >= NEW_START) {
        int p = atomicAdd(&g_count, 1);
        g_tok[p] = t;
    }
}

// ---------------- embedding copy: PERSISTENT, 148 blocks x 128 threads ----------
// One block per SM; footprint 128 thr x <=42 regs (~5K regs, 0 smem) leaves 60K
// regs free -> both 256x112-reg GEMM CTAs co-reside on every SM while this
// kernel streams. Batched 4x float4 per iteration gives ~1.2MB chip-wide bytes
// in flight — enough to pull multi-TB/s from just 19K threads.
// Masked tokens skipped (rows owned by fin2) -> no ordering dependency.
__global__ void __launch_bounds__(128, 12)
k_copy(const float* __restrict__ emb,
       const int*   __restrict__ ids,
       float*       __restrict__ out) {
    const int total  = NTOK * (DIM / 4);          // 13,107,200 chunks
    const int stride = CP_BLKS * 128;             // 18,944
    int i = blockIdx.x * 128 + threadIdx.x;
    for (; i < total; i += 4 * stride) {
        float4 v[4];
        int   tt[4];
        int   cc[4];
        bool  ok[4];
        #pragma unroll
        for (int j = 0; j < 4; j++) {
            int idx = i + j * stride;
            ok[j] = false;
            if (idx < total) {
                tt[j] = idx / (DIM / 4);
                cc[j] = idx % (DIM / 4);
                int id = ids[tt[j]];
                if (id < NEW_START) {
                    ok[j] = true;
                    v[j] = ((const float4*)(emb + (size_t)id * DIM))[cc[j]];
                }
            }
        }
        #pragma unroll
        for (int j = 0; j < 4; j++)
            if (ok[j])
                ((float4*)(out + (size_t)tt[j] * DIM))[cc[j]] = v[j];
    }
}

// ---------------- TF32 mma.sync split-K GEMM, cp.async 3-stage pipeline ----------
// AMODE 2: A row m = emb[ids[g_tok[m]]]  (independent of the copy)
// AMODE 0: A row m = g_H[m]
template<int AMODE>
__global__ void __launch_bounds__(256, 2)
k_mma(const int*   __restrict__ ids,
      const float* __restrict__ emb,
      const float* __restrict__ B,     // weights [K, N] row-major
      int N, int lda) {
    extern __shared__ char smbuf[];
    const uint32_t smb = smem_u32(smbuf);

    const int count = g_count;
    const int n0 = blockIdx.x * BN;
    const int kbase = blockIdx.y * KCHUNK;
    const int nstage = KCHUNK / BK;   // 5

    const int tid = threadIdx.x;      // 256
    const int wid = tid >> 5;
    const int lid = tid & 31;
    const int wm = wid >> 2;
    const int wn = wid & 3;
    const int fr = lid >> 2;
    const int fc = lid & 3;

    int am[2]  = { tid >> 3, (tid + 256) >> 3 };
    int akq[2] = { tid & 7,  (tid + 256) & 7 };
    const float* asrc[2];
    int asz[2];
    uint32_t adst[2];
    #pragma unroll
    for (int i = 0; i < 2; i++) {
        asz[i] = 0;
        asrc[i] = B;
        if (am[i] < count) {
            if (AMODE == 2) asrc[i] = emb + (size_t)ids[g_tok[am[i]]] * lda + akq[i] * 4;
            else            asrc[i] = g_H + (size_t)am[i] * lda + akq[i] * 4;
            asz[i] = 16;
        }
        adst[i] = smb + am[i] * (AS_LD * 4) + akq[i] * 16;
    }

    const float* bsrc[4];
    uint32_t bdst[4];
    #pragma unroll
    for (int j = 0; j < 4; j++) {
        int c = tid + 256 * j;
        int bk = c >> 5, nc = c & 31;
        bsrc[j] = B + (size_t)bk * N + n0 + nc * 4;
        bdst[j] = smb + A_BYTES + bk * B_ROW_B + nc * 16;
    }

    float acc[2][4][4];
    #pragma unroll
    for (int mi = 0; mi < 2; mi++)
        #pragma unroll
        for (int ni = 0; ni < 4; ni++)
            #pragma unroll
            for (int j = 0; j < 4; j++) acc[mi][ni][j] = 0.0f;

    auto issue = [&](int st) {
        const int off = (st % 3) * STAGE_B;
        const int k0 = kbase + st * BK;
        cp16(adst[0] + off, asrc[0] + k0, asz[0]);
        cp16(adst[1] + off, asrc[1] + k0, asz[1]);
        #pragma unroll
        for (int j = 0; j < 4; j++)
            cp16(bdst[j] + off, bsrc[j] + (size_t)k0 * N, 16);
    };

    issue(0); CP_COMMIT();
    issue(1); CP_COMMIT();

    for (int s = 0; s < nstage; s++) {
        if (s + 2 < nstage) issue(s + 2);
        CP_COMMIT();
        CP_WAIT2();
        __syncthreads();

        const uint32_t* As = (const uint32_t*)(smbuf + (s % 3) * STAGE_B);
        const uint32_t* Bs = (const uint32_t*)(smbuf + (s % 3) * STAGE_B + A_BYTES);

        #pragma unroll
        for (int kk = 0; kk < BK; kk += 8) {
            uint32_t a[2][4];
            #pragma unroll
            for (int mi = 0; mi < 2; mi++) {
                const int m0 = wm * 32 + mi * 16;
                a[mi][0] = As[(m0 + fr)     * AS_LD + kk + fc];
                a[mi][1] = As[(m0 + fr + 8) * AS_LD + kk + fc];
                a[mi][2] = As[(m0 + fr)     * AS_LD + kk + fc + 4];
                a[mi][3] = As[(m0 + fr + 8) * AS_LD + kk + fc + 4];
            }
            uint32_t b[4][2];
            #pragma unroll
            for (int ni = 0; ni < 4; ni++) {
                const int n = wn * 32 + ni * 8 + fr;
                b[ni][0] = Bs[(kk + fc)     * BS_LD + n];
                b[ni][1] = Bs[(kk + fc + 4) * BS_LD + n];
            }
            #pragma unroll
            for (int mi = 0; mi < 2; mi++)
                #pragma unroll
                for (int ni = 0; ni < 4; ni++)
                    mma_tf32(acc[mi][ni], a[mi], b[ni]);
        }
        __syncthreads();
    }

    // write partials — only rows < count (rows >= count never read by k_fin)
    float* pbase = g_P + (size_t)blockIdx.y * MAXM * N + n0;
    #pragma unroll
    for (int mi = 0; mi < 2; mi++) {
        const int row = wm * 32 + mi * 16 + fr;
        #pragma unroll
        for (int ni = 0; ni < 4; ni++) {
            const int col = wn * 32 + ni * 8 + 2 * fc;
            if (row < count) {
                float* p0 = pbase + (size_t)row * N + col;
                p0[0] = acc[mi][ni][0];
                p0[1] = acc[mi][ni][1];
            }
            if (row + 8 < count) {
                float* p1 = pbase + (size_t)(row + 8) * N + col;
                p1[0] = acc[mi][ni][2];
                p1[1] = acc[mi][ni][3];
            }
        }
    }
}

// ---------------- finalize: reduce splits + bias (+relu) + write ----------------
__global__ void k_fin(const float* __restrict__ bias,
                      float*       __restrict__ dst,
                      int N, int splits, int relu, int scatter, int ldc) {
    const int n = blockIdx.x * 256 + threadIdx.x;
    const int m = blockIdx.y;
    const int count = g_count;
    if (n >= N || m >= count) return;
    float s = bias[n];
    for (int i = 0; i < splits; i++)
        s += g_P[((size_t)i * MAXM + m) * N + n];
    if (relu) s = fmaxf(s, 0.f);
    if (scatter) dst[(size_t)g_tok[m] * ldc + n] = s;
    else         g_H[(size_t)m * ldc + n] = s;
}

// ---------------- fallback full-K GEMM (rows >= 64; early-exits normally) --------
template<int RELU, int AMODE, int SCATTER_C>
__global__ void k_gemm(const int*   __restrict__ ids,
                       const float* __restrict__ A,    // emb when AMODE==2
                       const float* __restrict__ B,
                       const float* __restrict__ bias,
                       float*       __restrict__ C,
                       int N, int K, int lda, int ldc) {
    __shared__ float As[FBK][FBM + 1];
    __shared__ float Bs[FBK][FBN];

    const int count = g_count;
    const int m0 = MAXM + blockIdx.y * FBM;
    if (m0 >= count) return;
    const int n0 = blockIdx.x * FBN;

    const int tid = threadIdx.x;
    const int tx = tid & 15;
    const int ty = tid >> 4;

    const int a_mi = tid >> 2;
    const int a_k  = (tid & 3) * 4;
    const int a_m  = m0 + a_mi;
    const float* arow = nullptr;
    if (a_m < count) {
        if (AMODE == 2) arow = A + (size_t)ids[g_tok[a_m]] * lda;
        else            arow = g_H + (size_t)a_m * lda;
    }

    const int b_kb = tid >> 4;
    const int b_n  = (tid & 15) * 4;

    float acc[FTM][FTN];
    #pragma unroll
    for (int i = 0; i < FTM; i++)
        #pragma unroll
        for (int j = 0; j < FTN; j++) acc[i][j] = 0.0f;

    for (int k0 = 0; k0 < K; k0 += FBK) {
        float4 va = make_float4(0.f, 0.f, 0.f, 0.f);
        if (arow) va = *(const float4*)(arow + k0 + a_k);
        As[a_k + 0][a_mi] = va.x;
        As[a_k + 1][a_mi] = va.y;
        As[a_k + 2][a_mi] = va.z;
        As[a_k + 3][a_mi] = va.w;

        float4 vb = *(const float4*)(B + (size_t)(k0 + b_kb) * N + n0 + b_n);
        *(float4*)&Bs[b_kb][b_n] = vb;

        __syncthreads();

        #pragma unroll
        for (int kk = 0; kk < FBK; kk++) {
            float a[FTM], b[FTN];
            #pragma unroll
            for (int i = 0; i < FTM; i++) a[i] = As[kk][ty * FTM + i];
            #pragma unroll
            for (int j = 0; j < FTN; j++) b[j] = Bs[kk][tx * FTN + j];
            #pragma unroll
            for (int i = 0; i < FTM; i++)
                #pragma unroll
                for (int j = 0; j < FTN; j++)
                    acc[i][j] = fmaf(a[i], b[j], acc[i][j]);
        }
        __syncthreads();
    }

    const int n = n0 + tx * FTN;
    float4 bv = *(const float4*)(bias + n);
    #pragma unroll
    for (int i = 0; i < FTM; i++) {
        int m = m0 + ty * FTM + i;
        if (m >= count) continue;
        float* crow;
        if (SCATTER_C) crow = C + (size_t)g_tok[m] * ldc;
        else           crow = g_H + (size_t)m * ldc;
        float4 v;
        v.x = acc[i][0] + bv.x;
        v.y = acc[i][1] + bv.y;
        v.z = acc[i][2] + bv.z;
        v.w = acc[i][3] + bv.w;
        if (RELU) {
            v.x = fmaxf(v.x, 0.f);
            v.y = fmaxf(v.y, 0.f);
            v.z = fmaxf(v.z, 0.f);
            v.w = fmaxf(v.w, 0.f);
        }
        *(float4*)(crow + n) = v;
    }
}

// ---------------- launch ----------------
extern "C" void kernel_launch(void* const* d_in, const int* in_sizes, int n_in,
                              void* d_out, int out_size) {
    const int*   ids = (const int*)  d_in[0];
    const float* emb = (const float*)d_in[1];
    const float* w1  = (const float*)d_in[2];
    const float* b1  = (const float*)d_in[3];
    const float* w2  = (const float*)d_in[4];
    const float* b2  = (const float*)d_in[5];
    float*       out = (float*)d_out;

    // lazily-created side stream + fork/join events (created on the first,
    // non-captured correctness call; record/wait inside capture is the
    // documented fork/join mechanism).
    static cudaStream_t s_copy = nullptr;
    static cudaEvent_t  e_fork = nullptr, e_join = nullptr;
    if (!s_copy) {
        cudaStreamCreateWithFlags(&s_copy, cudaStreamNonBlocking);
        cudaEventCreateWithFlags(&e_fork, cudaEventDisableTiming);
        cudaEventCreateWithFlags(&e_join, cudaEventDisableTiming);
    }

    cudaFuncSetAttribute(k_mma<2>, cudaFuncAttributeMaxDynamicSharedMemorySize, SMEM_B);
    cudaFuncSetAttribute(k_mma<0>, cudaFuncAttributeMaxDynamicSharedMemorySize, SMEM_B);

    // ---- fork: persistent copy, exactly 1 thin block per SM -> GEMM CTAs
    //      co-reside beside it on every SM for the whole run
    cudaEventRecord(e_fork, 0);
    cudaStreamWaitEvent(s_copy, e_fork, 0);
    k_copy<<<CP_BLKS, 128, 0, s_copy>>>(emb, ids, out);
    cudaEventRecord(e_join, s_copy);

    // ---- main stream: compact -> GEMM1 -> fin1 -> GEMM2 -> fin2
    k_reset<<<1, 1>>>();
    k_compact<<<NTOK / 256, 256>>>(ids);

    {
        dim3 gs(HID / BN, SPLITS1);                      // 50 x 20 = 1000 blocks
        k_mma<2><<<gs, 256, SMEM_B>>>(ids, emb, w1, HID, DIM);
        dim3 gf((HID + 255) / 256, MAXM);
        k_fin<<<gf, 256>>>(b1, nullptr, HID, SPLITS1, 1, 0, HID);
        dim3 gb(HID / FBN, (NTOK - MAXM) / FBM);
        k_gemm<1, 2, 0><<<gb, 256>>>(ids, emb, w1, b1, nullptr, HID, DIM, DIM, HID);
    }

    {
        dim3 gs(DIM / BN, SPLITS2);                      // 25 x 40 = 1000 blocks
        k_mma<0><<<gs, 256, SMEM_B>>>(ids, emb, w2, DIM, HID);
        // fin2 writes ONLY masked rows; copy skips them -> no copy dependency
        dim3 gf((DIM + 255) / 256, MAXM);
        k_fin<<<gf, 256>>>(b2, out, DIM, SPLITS2, 0, 1, DIM);
        dim3 gb(DIM / FBN, (NTOK - MAXM) / FBM);
        k_gemm<0, 0, 1><<<gb, 256>>>(ids, nullptr, w2, b2, out, DIM, HID, HID, DIM);
    }

    // ---- tail join: graph capture sees the side branch complete
    cudaStreamWaitEvent(0, e_join, 0);
}

// round 17
// speedup vs baseline: 2.6836x; 2.6836x over previous
#include <cuda_runtime.h>
#include <stdint.h>

#define DIM        3200
#define HID        6400
#define NTOK       16384   // 8 * 2048
#define NEW_START  32000

#define MAXM       64      // fast path covers rows [0, 64)
#define BN         128     // n per block
#define BK         32      // k per stage
#define KCHUNK     160     // k per split (5 stages)
#define SPLITS1    20      // layer1: K=3200
#define SPLITS2    40      // layer2: K=6400

// smem: 4-stage ring; per stage A[64][36] f32 (9216B) + B[32][136] f32 (17408B)
#define AS_LD      36
#define BS_LD      136     // 128 + 8 pad; conflict-free frag reads
#define A_BYTES    9216
#define B_ROW_B    (BS_LD * 4)                // 544
#define STAGE_B    (A_BYTES + BK * B_ROW_B)   // 26624
#define NSTAGES    4
#define SMEM_B     (NSTAGES * STAGE_B)        // 106496 (x2 CTAs = 213KB <= 228KB/SM)

// fallback tiling (rows >= 64; early-exits normally)
#define FBM 64
#define FBN 64
#define FBK 16
#define FTM 4
#define FTN 4
#define FB_YB 16   // y-blocks; each loops m-tiles internally

// ---------------- scratch (static device globals; no allocation) ----------------
__device__ int   g_count;
__device__ int   g_tok[NTOK];
__device__ float g_H[(size_t)NTOK * HID];            // hidden activations
__device__ float g_P[(size_t)8192000];               // split-K partials

// ---------------- helpers ----------------
__device__ __forceinline__ uint32_t smem_u32(const void* p) {
    uint32_t a;
    asm("{ .reg .u64 t; cvta.to.shared.u64 t, %1; cvt.u32.u64 %0, t; }" : "=r"(a) : "l"(p));
    return a;
}
__device__ __forceinline__ void cp16(uint32_t dst, const void* src, int srcsz) {
    asm volatile("cp.async.ca.shared.global [%0], [%1], 16, %2;"
                 :: "r"(dst), "l"(__cvta_generic_to_global(src)), "r"(srcsz) : "memory");
}
#define CP_COMMIT() asm volatile("cp.async.commit_group;" ::: "memory")
#define CP_WAIT3()  asm volatile("cp.async.wait_group 3;" ::: "memory")

__device__ __forceinline__ void mma_tf32(float* c, const uint32_t* a, const uint32_t* b) {
    asm volatile(
        "mma.sync.aligned.m16n8k8.row.col.f32.tf32.tf32.f32 "
        "{%0,%1,%2,%3}, {%4,%5,%6,%7}, {%8,%9}, {%0,%1,%2,%3};"
        : "+f"(c[0]), "+f"(c[1]), "+f"(c[2]), "+f"(c[3])
        : "r"(a[0]), "r"(a[1]), "r"(a[2]), "r"(a[3]), "r"(b[0]), "r"(b[1]));
}

// ---------------- kernel 0/1: reset + compact ----------------
__global__ void k_reset() { g_count = 0; }

__global__ void k_compact(const int* __restrict__ ids) {
    int t = blockIdx.x * blockDim.x + threadIdx.x;
    if (t < NTOK && ids[t] >= NEW_START) {
        int p = atomicAdd(&g_count, 1);
        g_tok[p] = t;
    }
}

// ---------------- embedding copy: one token per block (R13 proven form) ---------
// Low-priority stream; short blocks fill inter-kernel gaps and post-GEMM tail.
// Masked tokens skipped (rows owned by fin2) -> no ordering dependency.
__global__ void __launch_bounds__(256)
k_copy(const float* __restrict__ emb,
       const int*   __restrict__ ids,
       float*       __restrict__ out) {
    const int t = blockIdx.x;
    const int id = ids[t];
    if (id >= NEW_START) return;                 // row owned by MLP branch
    const float4* src = (const float4*)(emb + (size_t)id * DIM);
    float4*       dst = (float4*)(out + (size_t)t * DIM);
    #pragma unroll 4
    for (int i = threadIdx.x; i < DIM / 4; i += 256)
        dst[i] = src[i];
}

// ---------------- TF32 mma.sync split-K GEMM, cp.async 4-stage / depth-3 --------
// AMODE 2: A row m = emb[ids[g_tok[m]]]  (independent of the copy)
// AMODE 0: A row m = g_H[m]
template<int AMODE>
__global__ void __launch_bounds__(256, 2)
k_mma(const int*   __restrict__ ids,
      const float* __restrict__ emb,
      const float* __restrict__ B,     // weights [K, N] row-major
      int N, int lda) {
    extern __shared__ char smbuf[];
    const uint32_t smb = smem_u32(smbuf);

    const int count = g_count;
    const int n0 = blockIdx.x * BN;
    const int kbase = blockIdx.y * KCHUNK;
    const int nstage = KCHUNK / BK;   // 5

    const int tid = threadIdx.x;      // 256
    const int wid = tid >> 5;
    const int lid = tid & 31;
    const int wm = wid >> 2;
    const int wn = wid & 3;
    const int fr = lid >> 2;
    const int fc = lid & 3;

    int am[2]  = { tid >> 3, (tid + 256) >> 3 };
    int akq[2] = { tid & 7,  (tid + 256) & 7 };
    const float* asrc[2];
    int asz[2];
    uint32_t adst[2];
    #pragma unroll
    for (int i = 0; i < 2; i++) {
        asz[i] = 0;
        asrc[i] = B;
        if (am[i] < count) {
            if (AMODE == 2) asrc[i] = emb + (size_t)ids[g_tok[am[i]]] * lda + akq[i] * 4;
            else            asrc[i] = g_H + (size_t)am[i] * lda + akq[i] * 4;
            asz[i] = 16;
        }
        adst[i] = smb + am[i] * (AS_LD * 4) + akq[i] * 16;
    }

    const float* bsrc[4];
    uint32_t bdst[4];
    #pragma unroll
    for (int j = 0; j < 4; j++) {
        int c = tid + 256 * j;
        int bk = c >> 5, nc = c & 31;
        bsrc[j] = B + (size_t)bk * N + n0 + nc * 4;
        bdst[j] = smb + A_BYTES + bk * B_ROW_B + nc * 16;
    }

    float acc[2][4][4];
    #pragma unroll
    for (int mi = 0; mi < 2; mi++)
        #pragma unroll
        for (int ni = 0; ni < 4; ni++)
            #pragma unroll
            for (int j = 0; j < 4; j++) acc[mi][ni][j] = 0.0f;

    auto issue = [&](int st) {
        const int off = (st % NSTAGES) * STAGE_B;
        const int k0 = kbase + st * BK;
        cp16(adst[0] + off, asrc[0] + k0, asz[0]);
        cp16(adst[1] + off, asrc[1] + k0, asz[1]);
        #pragma unroll
        for (int j = 0; j < 4; j++)
            cp16(bdst[j] + off, bsrc[j] + (size_t)k0 * N, 16);
    };

    issue(0); CP_COMMIT();
    issue(1); CP_COMMIT();
    issue(2); CP_COMMIT();

    for (int s = 0; s < nstage; s++) {
        if (s + 3 < nstage) issue(s + 3);
        CP_COMMIT();
        CP_WAIT3();            // stage s complete; up to 3 stages in flight
        __syncthreads();

        const uint32_t* As = (const uint32_t*)(smbuf + (s % NSTAGES) * STAGE_B);
        const uint32_t* Bs = (const uint32_t*)(smbuf + (s % NSTAGES) * STAGE_B + A_BYTES);

        #pragma unroll
        for (int kk = 0; kk < BK; kk += 8) {
            uint32_t a[2][4];
            #pragma unroll
            for (int mi = 0; mi < 2; mi++) {
                const int m0 = wm * 32 + mi * 16;
                a[mi][0] = As[(m0 + fr)     * AS_LD + kk + fc];
                a[mi][1] = As[(m0 + fr + 8) * AS_LD + kk + fc];
                a[mi][2] = As[(m0 + fr)     * AS_LD + kk + fc + 4];
                a[mi][3] = As[(m0 + fr + 8) * AS_LD + kk + fc + 4];
            }
            uint32_t b[4][2];
            #pragma unroll
            for (int ni = 0; ni < 4; ni++) {
                const int n = wn * 32 + ni * 8 + fr;
                b[ni][0] = Bs[(kk + fc)     * BS_LD + n];
                b[ni][1] = Bs[(kk + fc + 4) * BS_LD + n];
            }
            #pragma unroll
            for (int mi = 0; mi < 2; mi++)
                #pragma unroll
                for (int ni = 0; ni < 4; ni++)
                    mma_tf32(acc[mi][ni], a[mi], b[ni]);
        }
        __syncthreads();       // ring distance NSTAGES: readers done before overwrite
    }

    // write partials — only rows < count (rows >= count never read by k_fin)
    float* pbase = g_P + (size_t)blockIdx.y * MAXM * N + n0;
    #pragma unroll
    for (int mi = 0; mi < 2; mi++) {
        const int row = wm * 32 + mi * 16 + fr;
        #pragma unroll
        for (int ni = 0; ni < 4; ni++) {
            const int col = wn * 32 + ni * 8 + 2 * fc;
            if (row < count) {
                float* p0 = pbase + (size_t)row * N + col;
                p0[0] = acc[mi][ni][0];
                p0[1] = acc[mi][ni][1];
            }
            if (row + 8 < count) {
                float* p1 = pbase + (size_t)(row + 8) * N + col;
                p1[0] = acc[mi][ni][2];
                p1[1] = acc[mi][ni][3];
            }
        }
    }
}

// ---------------- finalize: reduce splits + bias (+relu) + write ----------------
__global__ void k_fin(const float* __restrict__ bias,
                      float*       __restrict__ dst,
                      int N, int splits, int relu, int scatter, int ldc) {
    const int n = blockIdx.x * 256 + threadIdx.x;
    const int m = blockIdx.y;
    const int count = g_count;
    if (n >= N || m >= count) return;
    float s = bias[n];
    for (int i = 0; i < splits; i++)
        s += g_P[((size_t)i * MAXM + m) * N + n];
    if (relu) s = fmaxf(s, 0.f);
    if (scatter) dst[(size_t)g_tok[m] * ldc + n] = s;
    else         g_H[(size_t)m * ldc + n] = s;
}

// ---------------- fallback full-K GEMM (rows >= 64; m-tile LOOP, small grid) ----
// grid (N/FBN, FB_YB): block (x, y) handles m-tiles m0 = MAXM + (y + j*FB_YB)*FBM.
// Early-exits in one g_count load when count <= 64 (the common case).
template<int RELU, int AMODE, int SCATTER_C>
__global__ void k_gemm(const int*   __restrict__ ids,
                       const float* __restrict__ A,    // emb when AMODE==2
                       const float* __restrict__ B,
                       const float* __restrict__ bias,
                       float*       __restrict__ C,
                       int N, int K, int lda, int ldc) {
    __shared__ float As[FBK][FBM + 1];
    __shared__ float Bs[FBK][FBN];

    const int count = g_count;
    const int n0 = blockIdx.x * FBN;

    const int tid = threadIdx.x;
    const int tx = tid & 15;
    const int ty = tid >> 4;
    const int a_mi = tid >> 2;
    const int a_k  = (tid & 3) * 4;
    const int b_kb = tid >> 4;
    const int b_n  = (tid & 15) * 4;

    for (int m0 = MAXM + blockIdx.y * FBM; m0 < count; m0 += FB_YB * FBM) {
        const int a_m = m0 + a_mi;
        const float* arow = nullptr;
        if (a_m < count) {
            if (AMODE == 2) arow = A + (size_t)ids[g_tok[a_m]] * lda;
            else            arow = g_H + (size_t)a_m * lda;
        }

        float acc[FTM][FTN];
        #pragma unroll
        for (int i = 0; i < FTM; i++)
            #pragma unroll
            for (int j = 0; j < FTN; j++) acc[i][j] = 0.0f;

        for (int k0 = 0; k0 < K; k0 += FBK) {
            float4 va = make_float4(0.f, 0.f, 0.f, 0.f);
            if (arow) va = *(const float4*)(arow + k0 + a_k);
            As[a_k + 0][a_mi] = va.x;
            As[a_k + 1][a_mi] = va.y;
            As[a_k + 2][a_mi] = va.z;
            As[a_k + 3][a_mi] = va.w;

            float4 vb = *(const float4*)(B + (size_t)(k0 + b_kb) * N + n0 + b_n);
            *(float4*)&Bs[b_kb][b_n] = vb;

            __syncthreads();

            #pragma unroll
            for (int kk = 0; kk < FBK; kk++) {
                float a[FTM], b[FTN];
                #pragma unroll
                for (int i = 0; i < FTM; i++) a[i] = As[kk][ty * FTM + i];
                #pragma unroll
                for (int j = 0; j < FTN; j++) b[j] = Bs[kk][tx * FTN + j];
                #pragma unroll
                for (int i = 0; i < FTM; i++)
                    #pragma unroll
                    for (int j = 0; j < FTN; j++)
                        acc[i][j] = fmaf(a[i], b[j], acc[i][j]);
            }
            __syncthreads();
        }

        const int n = n0 + tx * FTN;
        float4 bv = *(const float4*)(bias + n);
        #pragma unroll
        for (int i = 0; i < FTM; i++) {
            int m = m0 + ty * FTM + i;
            if (m >= count) continue;
            float* crow;
            if (SCATTER_C) crow = C + (size_t)g_tok[m] * ldc;
            else           crow = g_H + (size_t)m * ldc;
            float4 v;
            v.x = acc[i][0] + bv.x;
            v.y = acc[i][1] + bv.y;
            v.z = acc[i][2] + bv.z;
            v.w = acc[i][3] + bv.w;
            if (RELU) {
                v.x = fmaxf(v.x, 0.f);
                v.y = fmaxf(v.y, 0.f);
                v.z = fmaxf(v.z, 0.f);
                v.w = fmaxf(v.w, 0.f);
            }
            *(float4*)(crow + n) = v;
        }
        __syncthreads();
    }
}

// ---------------- launch ----------------
extern "C" void kernel_launch(void* const* d_in, const int* in_sizes, int n_in,
                              void* d_out, int out_size) {
    const int*   ids = (const int*)  d_in[0];
    const float* emb = (const float*)d_in[1];
    const float* w1  = (const float*)d_in[2];
    const float* b1  = (const float*)d_in[3];
    const float* w2  = (const float*)d_in[4];
    const float* b2  = (const float*)d_in[5];
    float*       out = (float*)d_out;

    // lazily-created LOW-PRIORITY side stream + fork/join events (created on the
    // first, non-captured correctness call; record/wait inside capture is the
    // documented fork/join mechanism).
    static cudaStream_t s_copy = nullptr;
    static cudaEvent_t  e_fork = nullptr, e_join = nullptr;
    if (!s_copy) {
        int prio_lo = 0, prio_hi = 0;
        cudaDeviceGetStreamPriorityRange(&prio_lo, &prio_hi);
        cudaStreamCreateWithPriority(&s_copy, cudaStreamNonBlocking, prio_lo);
        cudaEventCreateWithFlags(&e_fork, cudaEventDisableTiming);
        cudaEventCreateWithFlags(&e_join, cudaEventDisableTiming);
    }

    cudaFuncSetAttribute(k_mma<2>, cudaFuncAttributeMaxDynamicSharedMemorySize, SMEM_B);
    cudaFuncSetAttribute(k_mma<0>, cudaFuncAttributeMaxDynamicSharedMemorySize, SMEM_B);

    // ---- fork: copy on LOW-priority stream (fills gaps + tail)
    cudaEventRecord(e_fork, 0);
    cudaStreamWaitEvent(s_copy, e_fork, 0);
    k_copy<<<NTOK, 256, 0, s_copy>>>(emb, ids, out);
    cudaEventRecord(e_join, s_copy);

    // ---- main stream: compact -> GEMM1 -> fin1 -> GEMM2 -> fin2
    k_reset<<<1, 1>>>();
    k_compact<<<NTOK / 256, 256>>>(ids);

    {
        dim3 gs(HID / BN, SPLITS1);                      // 50 x 20 = 1000 blocks
        k_mma<2><<<gs, 256, SMEM_B>>>(ids, emb, w1, HID, DIM);
        dim3 gf((HID + 255) / 256, MAXM);
        k_fin<<<gf, 256>>>(b1, nullptr, HID, SPLITS1, 1, 0, HID);
        dim3 gb(HID / FBN, FB_YB);                       // 100 x 16 (looped m-tiles)
        k_gemm<1, 2, 0><<<gb, 256>>>(ids, emb, w1, b1, nullptr, HID, DIM, DIM, HID);
    }

    {
        dim3 gs(DIM / BN, SPLITS2);                      // 25 x 40 = 1000 blocks
        k_mma<0><<<gs, 256, SMEM_B>>>(ids, emb, w2, DIM, HID);
        // fin2 writes ONLY masked rows; copy skips them -> no copy dependency
        dim3 gf((DIM + 255) / 256, MAXM);
        k_fin<<<gf, 256>>>(b2, out, DIM, SPLITS2, 0, 1, DIM);
        dim3 gb(DIM / FBN, FB_YB);                       // 50 x 16 (looped m-tiles)
        k_gemm<0, 0, 1><<<gb, 256>>>(ids, nullptr, w2, b2, out, DIM, HID, HID, DIM);
    }

    // ---- tail join: graph capture sees the side branch complete
    cudaStreamWaitEvent(0, e_join, 0);
}